// round 16
// baseline (speedup 1.0000x reference)
#include <cuda_runtime.h>
#include <cstdint>

#define BATCH 4
#define SEQ   2048
#define CIN   1024
#define HID   1024

// ---------------- scratch (__device__ globals; alloc APIs forbidden) -------
__device__ float g_M   [CIN * CIN];                 // 4 MB  (Wq@Wk^T * 2^-5, tf32)
__device__ float g_qm  [BATCH * SEQ * CIN];         // 32 MB (q@M, tf32-rounded)
__device__ float g_vp  [BATCH * SEQ * HID];         // 32 MB (v@Wq, tf32-rounded)
__device__ float g_P   [(long)BATCH * SEQ * SEQ];   // 64 MB (unnormalized exp'd probs)
__device__ float g_psum[BATCH * 16 * SEQ];          // 512 KB (partial row sums)

// ---------------- helpers ---------------------------------------------------
__device__ __forceinline__ uint32_t smem_u32(const void* p) {
    uint32_t r;
    asm("{ .reg .u64 t; cvta.to.shared.u64 t, %1; cvt.u32.u64 %0, t; }"
        : "=r"(r) : "l"(p));
    return r;
}
__device__ __forceinline__ void cpa16(uint32_t dst, const void* src) {
    asm volatile("cp.async.cg.shared.global [%0], [%1], 16;" :: "r"(dst), "l"(src));
}
__device__ __forceinline__ uint32_t f2tf(float x) {
    uint32_t r;
    asm("cvt.rna.tf32.f32 %0, %1;" : "=r"(r) : "f"(x));
    return r;
}
__device__ __forceinline__ float roundtf(float x) { return __uint_as_float(f2tf(x)); }
__device__ __forceinline__ void mma_tf32(float* c, const uint32_t* a, const uint32_t* b) {
    asm volatile("mma.sync.aligned.m16n8k8.row.col.f32.tf32.tf32.f32 "
                 "{%0,%1,%2,%3}, {%4,%5,%6,%7}, {%8,%9}, {%0,%1,%2,%3};"
                 : "+f"(c[0]), "+f"(c[1]), "+f"(c[2]), "+f"(c[3])
                 : "r"(a[0]), "r"(a[1]), "r"(a[2]), "r"(a[3]),
                   "r"(b[0]), "r"(b[1]));
}

// ---------------- tensor-core tf32 GEMM core (R10 config) -------------------
#define NSTAGE      3
#define STAGE_FLTS  8192          // A 4096 + B 4096 floats (32 KB)
#define GEMM_SMEM   (NSTAGE * STAGE_FLTS * 4)   // 98304 B
#define GTHREADS    128

template<int EPI, bool CVTA, bool CVTB, bool ROUND_OUT, bool BNN>
__device__ __forceinline__
void gemm_body(const float* __restrict__ A, const float* __restrict__ B,
               float* __restrict__ C, int ldA, int ldB, int ldC,
               int KT, int bm, int bn, float alphaOut,
               float* __restrict__ ps, int psN, bool diag)
{
    extern __shared__ float sm[];
    const uint32_t sbase = smem_u32(sm);
    const int tid  = threadIdx.x;
    const int lane = tid & 31;
    const int wid  = tid >> 5;        // 0..3
    const int wm = (wid >> 1) * 64;
    const int wn = (wid & 1) * 64;
    const int qr = lane >> 2;         // 0..7
    const int qc = lane & 3;          // 0..3
    const int xm = qr << 2;

    const int arow = tid >> 3;            // 0..15
    const int akq  = (tid & 7) * 4;
    const float* Abase = A + (long)(bm * 128 + arow) * ldA + akq;
    const long aStride = (long)16 * ldA;
    const uint32_t adst0 = sbase + (uint32_t)(arow * 32 + (akq ^ ((arow & 7) << 2))) * 4;

    const float* Bbase; long bStride; long bStageStep; uint32_t bdst0;
    if (BNN) {
        const int bk  = tid >> 5;         // 0..3
        const int bn4 = (tid & 31) * 4;
        Bbase = B + (long)bk * ldB + bn * 128 + bn4;
        bStride = (long)4 * ldB;
        bStageStep = (long)32 * ldB;
        bdst0 = sbase + 16384u + (uint32_t)(bk * 128 + (bn4 ^ ((bk & 3) << 3))) * 4;
    } else {
        Bbase = B + (long)(bn * 128 + arow) * ldB + akq;
        bStride = (long)16 * ldB;
        bStageStep = 32;
        bdst0 = sbase + 16384u + (uint32_t)(arow * 32 + (akq ^ ((arow & 7) << 2))) * 4;
    }

    auto issue_stage = [&](int s) {
        const uint32_t soff = (uint32_t)((s % NSTAGE) * (STAGE_FLTS * 4));
        const float* ap = Abase + s * 32;
        uint32_t ad = adst0 + soff;
#pragma unroll
        for (int t = 0; t < 8; t++) { cpa16(ad, ap); ap += aStride; ad += 2048; }
        const float* bp = Bbase + s * bStageStep;
        uint32_t bd = bdst0 + soff;
#pragma unroll
        for (int t = 0; t < 8; t++) { cpa16(bd, bp); bp += bStride; bd += 2048; }
    };

    int npr[8];
    if (BNN) {
#pragma unroll
        for (int nt = 0; nt < 8; nt++)
            npr[nt] = (wn + nt * 8 + qr) ^ (qc << 3);
    }

    auto load_frags = [&](const float* As, const float* Bs, int ks,
                          uint32_t af[4][4], uint32_t bf[8][2]) {
        const int k0 = ks * 8;
        const int c0 = (k0 + qc) ^ xm;
        const int c1 = (k0 + 4 + qc) ^ xm;
#pragma unroll
        for (int mt = 0; mt < 4; mt++) {
            int r  = wm + mt * 16 + qr;
            int r8 = r + 8;
            if (CVTA) {
                af[mt][0] = f2tf(As[r  * 32 + c0]);
                af[mt][1] = f2tf(As[r8 * 32 + c0]);
                af[mt][2] = f2tf(As[r  * 32 + c1]);
                af[mt][3] = f2tf(As[r8 * 32 + c1]);
            } else {
                af[mt][0] = __float_as_uint(As[r  * 32 + c0]);
                af[mt][1] = __float_as_uint(As[r8 * 32 + c0]);
                af[mt][2] = __float_as_uint(As[r  * 32 + c1]);
                af[mt][3] = __float_as_uint(As[r8 * 32 + c1]);
            }
        }
#pragma unroll
        for (int nt = 0; nt < 8; nt++) {
            if (BNN) {
                float v0 = Bs[(k0 + qc)     * 128 + npr[nt]];
                float v1 = Bs[(k0 + 4 + qc) * 128 + npr[nt]];
                bf[nt][0] = CVTB ? f2tf(v0) : __float_as_uint(v0);
                bf[nt][1] = CVTB ? f2tf(v1) : __float_as_uint(v1);
            } else {
                int n = wn + nt * 8 + qr;
                float v0 = Bs[n * 32 + c0];
                float v1 = Bs[n * 32 + c1];
                bf[nt][0] = CVTB ? f2tf(v0) : __float_as_uint(v0);
                bf[nt][1] = CVTB ? f2tf(v1) : __float_as_uint(v1);
            }
        }
    };

    float acc[4][8][4];
#pragma unroll
    for (int mt = 0; mt < 4; mt++)
#pragma unroll
        for (int nt = 0; nt < 8; nt++)
#pragma unroll
            for (int i = 0; i < 4; i++) acc[mt][nt][i] = 0.0f;

    auto run_mma = [&](uint32_t af[4][4], uint32_t bf[8][2]) {
#pragma unroll
        for (int mt = 0; mt < 4; mt++)
#pragma unroll
            for (int nt = 0; nt < 8; nt++)
                mma_tf32(acc[mt][nt], af[mt], bf[nt]);
    };

#pragma unroll
    for (int s = 0; s < 2; s++) {
        issue_stage(s);
        asm volatile("cp.async.commit_group;" ::: "memory");
    }

    for (int kt = 0; kt < KT; kt++) {
        asm volatile("cp.async.wait_group 1;" ::: "memory");
        __syncthreads();

        const float* As = sm + (kt % NSTAGE) * STAGE_FLTS;
        const float* Bs = As + 4096;

        uint32_t afA[4][4], bfA[8][2], afB[4][4], bfB[8][2];
        load_frags(As, Bs, 0, afA, bfA);

        int sf = kt + 2;
        if (sf < KT) issue_stage(sf);
        asm volatile("cp.async.commit_group;" ::: "memory");

        load_frags(As, Bs, 1, afB, bfB);
        run_mma(afA, bfA);
        load_frags(As, Bs, 2, afA, bfA);
        run_mma(afB, bfB);
        load_frags(As, Bs, 3, afB, bfB);
        run_mma(afA, bfA);
        run_mma(afB, bfB);
    }

    if (EPI == 1) {
        // causal exp epilogue + per-row partial sums (no atomics)
        asm volatile("cp.async.wait_group 0;" ::: "memory");
        __syncthreads();
        float* spr = sm;
        float rsum[4][2];
#pragma unroll
        for (int mt = 0; mt < 4; mt++) { rsum[mt][0] = 0.0f; rsum[mt][1] = 0.0f; }

#pragma unroll
        for (int mt = 0; mt < 4; mt++) {
            int r0g = bm * 128 + wm + mt * 16 + qr;
#pragma unroll
            for (int nt = 0; nt < 8; nt++) {
                int colg = bn * 128 + wn + nt * 8 + 2 * qc;
                float e0 = 0.f, e1 = 0.f, e2 = 0.f, e3 = 0.f;
                if (!diag || colg     <= r0g)     e0 = __expf(acc[mt][nt][0]);
                if (!diag || colg + 1 <= r0g)     e1 = __expf(acc[mt][nt][1]);
                if (!diag || colg     <= r0g + 8) e2 = __expf(acc[mt][nt][2]);
                if (!diag || colg + 1 <= r0g + 8) e3 = __expf(acc[mt][nt][3]);
                rsum[mt][0] += e0 + e1;
                rsum[mt][1] += e2 + e3;
                *(float2*)&C[(long)r0g * ldC + colg] =
                    make_float2(roundtf(e0), roundtf(e1));
                *(float2*)&C[(long)(r0g + 8) * ldC + colg] =
                    make_float2(roundtf(e2), roundtf(e3));
            }
        }
#pragma unroll
        for (int mt = 0; mt < 4; mt++)
#pragma unroll
            for (int h = 0; h < 2; h++) {
                rsum[mt][h] += __shfl_xor_sync(~0u, rsum[mt][h], 1);
                rsum[mt][h] += __shfl_xor_sync(~0u, rsum[mt][h], 2);
            }
        if (qc == 0) {
            int half = wn >> 6;
#pragma unroll
            for (int mt = 0; mt < 4; mt++) {
                int lr = wm + mt * 16 + qr;
                spr[lr * 2 + half]       = rsum[mt][0];
                spr[(lr + 8) * 2 + half] = rsum[mt][1];
            }
        }
        __syncthreads();
        if (tid < 128) ps[tid] = spr[tid * 2] + spr[tid * 2 + 1];
        return;
    }

    if (EPI == 2) {
        // rowsum gather + reciprocal
        asm volatile("cp.async.wait_group 0;" ::: "memory");
        __syncthreads();
        float* sinv = sm;
        if (tid < 128) {
            float s = 0.0f;
            for (int j = 0; j < psN; j++) s += ps[(long)j * SEQ + tid];
            sinv[tid] = 1.0f / s;
        }
        __syncthreads();
#pragma unroll
        for (int mt = 0; mt < 4; mt++) {
            int lr = wm + mt * 16 + qr;
            int r  = bm * 128 + lr;
            float i0 = sinv[lr], i1 = sinv[lr + 8];
#pragma unroll
            for (int nt = 0; nt < 8; nt++) {
                int col = bn * 128 + wn + nt * 8 + 2 * qc;
                *(float2*)&C[(long)r * ldC + col] =
                    make_float2(acc[mt][nt][0] * i0, acc[mt][nt][1] * i0);
                *(float2*)&C[(long)(r + 8) * ldC + col] =
                    make_float2(acc[mt][nt][2] * i1, acc[mt][nt][3] * i1);
            }
        }
        return;
    }

    // EPI == 0: plain store
#pragma unroll
    for (int mt = 0; mt < 4; mt++) {
        int r = bm * 128 + wm + mt * 16 + qr;
#pragma unroll
        for (int nt = 0; nt < 8; nt++) {
            int col = bn * 128 + wn + nt * 8 + 2 * qc;
            float o0 = acc[mt][nt][0] * alphaOut, o1 = acc[mt][nt][1] * alphaOut;
            float o2 = acc[mt][nt][2] * alphaOut, o3 = acc[mt][nt][3] * alphaOut;
            if (ROUND_OUT) { o0 = roundtf(o0); o1 = roundtf(o1);
                             o2 = roundtf(o2); o3 = roundtf(o3); }
            *(float2*)&C[(long)r * ldC + col]       = make_float2(o0, o1);
            *(float2*)&C[(long)(r + 8) * ldC + col] = make_float2(o2, o3);
        }
    }
}

// M = (Wq @ Wk^T) * 2^-5  (NT)
__global__ __launch_bounds__(GTHREADS, 2)
void m_gemm(const float* __restrict__ Wq, const float* __restrict__ Wk,
            float* __restrict__ M)
{
    gemm_body<0, true, true, true, false>(Wq, Wk, M, HID, HID, CIN, HID / 32,
                                          blockIdx.y, blockIdx.x, 1.0f / 32.0f,
                                          nullptr, 0, false);
}

// qm = q @ M for ONE batch (pointers pre-offset). Grid (8, 16).
__global__ __launch_bounds__(GTHREADS, 2)
void qm_gemm(const float* __restrict__ qz, const float* __restrict__ M,
             float* __restrict__ qmz)
{
    gemm_body<0, true, false, true, true>(qz, M, qmz, CIN, CIN, CIN, CIN / 32,
                                          blockIdx.y, blockIdx.x, 1.0f,
                                          nullptr, 0, false);
}

// v projection (side stream). vp = v @ Wq (faithful bug).
__global__ __launch_bounds__(GTHREADS, 2)
void proj_v(const float* __restrict__ vin, const float* __restrict__ Wq,
            float* __restrict__ vp)
{
    gemm_body<0, true, false, true, true>(vin, Wq, vp, CIN, HID, HID, CIN / 32,
                                          blockIdx.y, blockIdx.x, 1.0f,
                                          nullptr, 0, false);
}

// P' = exp(qm @ k^T) + partial sums, ONE batch. Triangular grid (136), heavy first.
__global__ __launch_bounds__(GTHREADS, 2)
void s_gemm(const float* __restrict__ qmz, const float* __restrict__ kz,
            float* __restrict__ Pz, float* __restrict__ psz)
{
    int idx = 135 - blockIdx.x;           // heavy (high-bm) first
    int acc = 0, bm = 0;
    while (acc + bm + 1 <= idx) { acc += bm + 1; bm++; }
    int bn = idx - acc;
    float* ps = psz + (long)bn * SEQ + bm * 128;
    gemm_body<1, false, true, false, false>(qmz, kz, Pz,
                                            CIN, CIN, SEQ, CIN / 32, bm, bn, 1.0f,
                                            ps, 0, bn == bm);
}

// out = (P' @ vp) / rowsum, ONE batch. Grid (8, 16), heavy first.
__global__ __launch_bounds__(GTHREADS, 2)
void pv_gemm(const float* __restrict__ Pz, const float* __restrict__ vpz,
             float* __restrict__ outz, const float* __restrict__ psz)
{
    const int bm = (int)(gridDim.y - 1 - blockIdx.y);   // heavy first
    const int bn = blockIdx.x;
    const int KT = (bm + 1) * 4;
    float* ps = const_cast<float*>(psz) + bm * 128;
    gemm_body<2, false, false, false, true>(Pz, vpz, outz,
                                            SEQ, HID, HID, KT, bm, bn, 1.0f,
                                            ps, bm + 1, false);
}

// ---------------- launch: 2-stream per-batch pipelined graph ----------------
// Stream budget lesson from R15: extra streams cost ~512KB device pool each
// and trip the allocation guard at 4; exactly ONE side stream (R12-R14
// passing configs) is safe. Express the per-batch pipeline on 2 streams:
//   main: m -> [qm->s->pv](0) -> [..](1) -> [..](2)
//   s2  : proj_v -> [qm->s->pv](3)
// Both queues stay busy for nearly the whole run, keeping two different
// kernels co-resident per SM (the regime where measured aggregate pace rose
// from ~150 to ~173 TF/s).
extern "C" void kernel_launch(void* const* d_in, const int* in_sizes, int n_in,
                              void* d_out, int out_size)
{
    const float* kin = (const float*)d_in[1];
    const float* qin = (const float*)d_in[2];
    const float* vin = (const float*)d_in[3];
    const float* Wk  = (const float*)d_in[4];
    const float* Wq  = (const float*)d_in[5];
    float* out = (float*)d_out;

    float *M, *qm, *vp, *P, *psum;
    cudaGetSymbolAddress((void**)&M,    g_M);
    cudaGetSymbolAddress((void**)&qm,   g_qm);
    cudaGetSymbolAddress((void**)&vp,   g_vp);
    cudaGetSymbolAddress((void**)&P,    g_P);
    cudaGetSymbolAddress((void**)&psum, g_psum);

    cudaFuncSetAttribute(m_gemm,  cudaFuncAttributeMaxDynamicSharedMemorySize, GEMM_SMEM);
    cudaFuncSetAttribute(qm_gemm, cudaFuncAttributeMaxDynamicSharedMemorySize, GEMM_SMEM);
    cudaFuncSetAttribute(proj_v,  cudaFuncAttributeMaxDynamicSharedMemorySize, GEMM_SMEM);
    cudaFuncSetAttribute(s_gemm,  cudaFuncAttributeMaxDynamicSharedMemorySize, GEMM_SMEM);
    cudaFuncSetAttribute(pv_gemm, cudaFuncAttributeMaxDynamicSharedMemorySize, GEMM_SMEM);

    dim3 gblk(GTHREADS);

    // ONE side stream + 4 events; created per call, never destroyed
    // (few calls total; destroy-during-capture is hazardous).
    cudaStream_t s2;
    cudaStreamCreateWithFlags(&s2, cudaStreamNonBlocking);
    cudaEvent_t eStart, eM, eV, eJ;
    cudaEventCreateWithFlags(&eStart, cudaEventDisableTiming);
    cudaEventCreateWithFlags(&eM,     cudaEventDisableTiming);
    cudaEventCreateWithFlags(&eV,     cudaEventDisableTiming);
    cudaEventCreateWithFlags(&eJ,     cudaEventDisableTiming);

    auto ioff = [](int z) { return (long)z * SEQ * CIN; };
    auto Poff = [](int z) { return (long)z * SEQ * SEQ; };
    auto soff = [](int z) { return (long)z * 16 * SEQ; };

    // fork
    cudaEventRecord(eStart, 0);
    cudaStreamWaitEvent(s2, eStart, 0);

    // s2: v projection for ALL batches, then batch-3 pipeline
    proj_v<<<dim3(HID / 128, (BATCH * SEQ) / 128, 1), gblk, GEMM_SMEM, s2>>>(vin, Wq, vp);
    cudaEventRecord(eV, s2);

    // main: tiny M
    m_gemm<<<dim3(CIN / 128, CIN / 128, 1), gblk, GEMM_SMEM>>>(Wq, Wk, M);
    cudaEventRecord(eM, 0);

    // s2: batch-3 pipeline (after M; vp ordered in-stream)
    cudaStreamWaitEvent(s2, eM, 0);
    qm_gemm<<<dim3(CIN / 128, SEQ / 128, 1), gblk, GEMM_SMEM, s2>>>(
        qin + ioff(3), M, qm + ioff(3));
    s_gemm<<<dim3(136, 1, 1), gblk, GEMM_SMEM, s2>>>(
        qm + ioff(3), kin + ioff(3), P + Poff(3), psum + soff(3));
    pv_gemm<<<dim3(HID / 128, SEQ / 128, 1), gblk, GEMM_SMEM, s2>>>(
        P + Poff(3), vp + ioff(3), out + ioff(3), psum + soff(3));
    cudaEventRecord(eJ, s2);

    // main: batch 0,1,2 pipelines (pv needs vp -> wait eV once, before pv(0))
    for (int z = 0; z < 3; z++) {
        qm_gemm<<<dim3(CIN / 128, SEQ / 128, 1), gblk, GEMM_SMEM>>>(
            qin + ioff(z), M, qm + ioff(z));
        s_gemm<<<dim3(136, 1, 1), gblk, GEMM_SMEM>>>(
            qm + ioff(z), kin + ioff(z), P + Poff(z), psum + soff(z));
        if (z == 0) cudaStreamWaitEvent(0, eV, 0);
        pv_gemm<<<dim3(HID / 128, SEQ / 128, 1), gblk, GEMM_SMEM>>>(
            P + Poff(z), vp + ioff(z), out + ioff(z), psum + soff(z));
    }

    // join
    cudaStreamWaitEvent(0, eJ, 0);
}

// round 17
// speedup vs baseline: 1.1722x; 1.1722x over previous
#include <cuda_runtime.h>
#include <cstdint>

#define BATCH 4
#define SEQ   2048
#define CIN   1024
#define HID   1024

// ---------------- scratch (__device__ globals; alloc APIs forbidden) -------
__device__ float g_M   [CIN * CIN];                 // 4 MB  (Wq@Wk^T * 2^-5, tf32)
__device__ float g_qm  [BATCH * SEQ * CIN];         // 32 MB (q@M, tf32-rounded)
__device__ float g_vp  [BATCH * SEQ * HID];         // 32 MB (v@Wq, tf32-rounded)
__device__ float g_P   [(long)BATCH * SEQ * SEQ];   // 64 MB (unnormalized exp'd probs)
__device__ float g_psum[BATCH * 16 * SEQ];          // 512 KB (partial row sums)

// ---------------- helpers ---------------------------------------------------
__device__ __forceinline__ uint32_t smem_u32(const void* p) {
    uint32_t r;
    asm("{ .reg .u64 t; cvta.to.shared.u64 t, %1; cvt.u32.u64 %0, t; }"
        : "=r"(r) : "l"(p));
    return r;
}
__device__ __forceinline__ void cpa16(uint32_t dst, const void* src) {
    asm volatile("cp.async.cg.shared.global [%0], [%1], 16;" :: "r"(dst), "l"(src));
}
__device__ __forceinline__ uint32_t f2tf(float x) {
    uint32_t r;
    asm("cvt.rna.tf32.f32 %0, %1;" : "=r"(r) : "f"(x));
    return r;
}
__device__ __forceinline__ float roundtf(float x) { return __uint_as_float(f2tf(x)); }
__device__ __forceinline__ void mma_tf32(float* c, const uint32_t* a, const uint32_t* b) {
    asm volatile("mma.sync.aligned.m16n8k8.row.col.f32.tf32.tf32.f32 "
                 "{%0,%1,%2,%3}, {%4,%5,%6,%7}, {%8,%9}, {%0,%1,%2,%3};"
                 : "+f"(c[0]), "+f"(c[1]), "+f"(c[2]), "+f"(c[3])
                 : "r"(a[0]), "r"(a[1]), "r"(a[2]), "r"(a[3]),
                   "r"(b[0]), "r"(b[1]));
}

// ---------------- tensor-core tf32 GEMM core (R10 config) -------------------
#define NSTAGE      3
#define STAGE_FLTS  8192          // A 4096 + B 4096 floats (32 KB)
#define GEMM_SMEM   (NSTAGE * STAGE_FLTS * 4)   // 98304 B
#define GTHREADS    128

template<int EPI, bool CVTA, bool CVTB, bool ROUND_OUT, bool BNN>
__device__ __forceinline__
void gemm_body(const float* __restrict__ A, const float* __restrict__ B,
               float* __restrict__ C, int ldA, int ldB, int ldC,
               int KT, int bm, int bn, float alphaOut,
               float* __restrict__ ps, int psN, bool diag)
{
    extern __shared__ float sm[];
    const uint32_t sbase = smem_u32(sm);
    const int tid  = threadIdx.x;
    const int lane = tid & 31;
    const int wid  = tid >> 5;        // 0..3
    const int wm = (wid >> 1) * 64;
    const int wn = (wid & 1) * 64;
    const int qr = lane >> 2;         // 0..7
    const int qc = lane & 3;          // 0..3
    const int xm = qr << 2;

    const int arow = tid >> 3;            // 0..15
    const int akq  = (tid & 7) * 4;
    const float* Abase = A + (long)(bm * 128 + arow) * ldA + akq;
    const long aStride = (long)16 * ldA;
    const uint32_t adst0 = sbase + (uint32_t)(arow * 32 + (akq ^ ((arow & 7) << 2))) * 4;

    const float* Bbase; long bStride; long bStageStep; uint32_t bdst0;
    if (BNN) {
        const int bk  = tid >> 5;         // 0..3
        const int bn4 = (tid & 31) * 4;
        Bbase = B + (long)bk * ldB + bn * 128 + bn4;
        bStride = (long)4 * ldB;
        bStageStep = (long)32 * ldB;
        bdst0 = sbase + 16384u + (uint32_t)(bk * 128 + (bn4 ^ ((bk & 3) << 3))) * 4;
    } else {
        Bbase = B + (long)(bn * 128 + arow) * ldB + akq;
        bStride = (long)16 * ldB;
        bStageStep = 32;
        bdst0 = sbase + 16384u + (uint32_t)(arow * 32 + (akq ^ ((arow & 7) << 2))) * 4;
    }

    auto issue_stage = [&](int s) {
        const uint32_t soff = (uint32_t)((s % NSTAGE) * (STAGE_FLTS * 4));
        const float* ap = Abase + s * 32;
        uint32_t ad = adst0 + soff;
#pragma unroll
        for (int t = 0; t < 8; t++) { cpa16(ad, ap); ap += aStride; ad += 2048; }
        const float* bp = Bbase + s * bStageStep;
        uint32_t bd = bdst0 + soff;
#pragma unroll
        for (int t = 0; t < 8; t++) { cpa16(bd, bp); bp += bStride; bd += 2048; }
    };

    int npr[8];
    if (BNN) {
#pragma unroll
        for (int nt = 0; nt < 8; nt++)
            npr[nt] = (wn + nt * 8 + qr) ^ (qc << 3);
    }

    auto load_frags = [&](const float* As, const float* Bs, int ks,
                          uint32_t af[4][4], uint32_t bf[8][2]) {
        const int k0 = ks * 8;
        const int c0 = (k0 + qc) ^ xm;
        const int c1 = (k0 + 4 + qc) ^ xm;
#pragma unroll
        for (int mt = 0; mt < 4; mt++) {
            int r  = wm + mt * 16 + qr;
            int r8 = r + 8;
            if (CVTA) {
                af[mt][0] = f2tf(As[r  * 32 + c0]);
                af[mt][1] = f2tf(As[r8 * 32 + c0]);
                af[mt][2] = f2tf(As[r  * 32 + c1]);
                af[mt][3] = f2tf(As[r8 * 32 + c1]);
            } else {
                af[mt][0] = __float_as_uint(As[r  * 32 + c0]);
                af[mt][1] = __float_as_uint(As[r8 * 32 + c0]);
                af[mt][2] = __float_as_uint(As[r  * 32 + c1]);
                af[mt][3] = __float_as_uint(As[r8 * 32 + c1]);
            }
        }
#pragma unroll
        for (int nt = 0; nt < 8; nt++) {
            if (BNN) {
                float v0 = Bs[(k0 + qc)     * 128 + npr[nt]];
                float v1 = Bs[(k0 + 4 + qc) * 128 + npr[nt]];
                bf[nt][0] = CVTB ? f2tf(v0) : __float_as_uint(v0);
                bf[nt][1] = CVTB ? f2tf(v1) : __float_as_uint(v1);
            } else {
                int n = wn + nt * 8 + qr;
                float v0 = Bs[n * 32 + c0];
                float v1 = Bs[n * 32 + c1];
                bf[nt][0] = CVTB ? f2tf(v0) : __float_as_uint(v0);
                bf[nt][1] = CVTB ? f2tf(v1) : __float_as_uint(v1);
            }
        }
    };

    float acc[4][8][4];
#pragma unroll
    for (int mt = 0; mt < 4; mt++)
#pragma unroll
        for (int nt = 0; nt < 8; nt++)
#pragma unroll
            for (int i = 0; i < 4; i++) acc[mt][nt][i] = 0.0f;

    auto run_mma = [&](uint32_t af[4][4], uint32_t bf[8][2]) {
#pragma unroll
        for (int mt = 0; mt < 4; mt++)
#pragma unroll
            for (int nt = 0; nt < 8; nt++)
                mma_tf32(acc[mt][nt], af[mt], bf[nt]);
    };

#pragma unroll
    for (int s = 0; s < 2; s++) {
        issue_stage(s);
        asm volatile("cp.async.commit_group;" ::: "memory");
    }

    for (int kt = 0; kt < KT; kt++) {
        asm volatile("cp.async.wait_group 1;" ::: "memory");
        __syncthreads();

        const float* As = sm + (kt % NSTAGE) * STAGE_FLTS;
        const float* Bs = As + 4096;

        uint32_t afA[4][4], bfA[8][2], afB[4][4], bfB[8][2];
        load_frags(As, Bs, 0, afA, bfA);

        int sf = kt + 2;
        if (sf < KT) issue_stage(sf);
        asm volatile("cp.async.commit_group;" ::: "memory");

        load_frags(As, Bs, 1, afB, bfB);
        run_mma(afA, bfA);
        load_frags(As, Bs, 2, afA, bfA);
        run_mma(afB, bfB);
        load_frags(As, Bs, 3, afB, bfB);
        run_mma(afA, bfA);
        run_mma(afB, bfB);
    }

    if (EPI == 1) {
        // causal exp epilogue + per-row partial sums (no atomics)
        asm volatile("cp.async.wait_group 0;" ::: "memory");
        __syncthreads();
        float* spr = sm;
        float rsum[4][2];
#pragma unroll
        for (int mt = 0; mt < 4; mt++) { rsum[mt][0] = 0.0f; rsum[mt][1] = 0.0f; }

#pragma unroll
        for (int mt = 0; mt < 4; mt++) {
            int r0g = bm * 128 + wm + mt * 16 + qr;
#pragma unroll
            for (int nt = 0; nt < 8; nt++) {
                int colg = bn * 128 + wn + nt * 8 + 2 * qc;
                float e0 = 0.f, e1 = 0.f, e2 = 0.f, e3 = 0.f;
                if (!diag || colg     <= r0g)     e0 = __expf(acc[mt][nt][0]);
                if (!diag || colg + 1 <= r0g)     e1 = __expf(acc[mt][nt][1]);
                if (!diag || colg     <= r0g + 8) e2 = __expf(acc[mt][nt][2]);
                if (!diag || colg + 1 <= r0g + 8) e3 = __expf(acc[mt][nt][3]);
                rsum[mt][0] += e0 + e1;
                rsum[mt][1] += e2 + e3;
                *(float2*)&C[(long)r0g * ldC + colg] =
                    make_float2(roundtf(e0), roundtf(e1));
                *(float2*)&C[(long)(r0g + 8) * ldC + colg] =
                    make_float2(roundtf(e2), roundtf(e3));
            }
        }
#pragma unroll
        for (int mt = 0; mt < 4; mt++)
#pragma unroll
            for (int h = 0; h < 2; h++) {
                rsum[mt][h] += __shfl_xor_sync(~0u, rsum[mt][h], 1);
                rsum[mt][h] += __shfl_xor_sync(~0u, rsum[mt][h], 2);
            }
        if (qc == 0) {
            int half = wn >> 6;
#pragma unroll
            for (int mt = 0; mt < 4; mt++) {
                int lr = wm + mt * 16 + qr;
                spr[lr * 2 + half]       = rsum[mt][0];
                spr[(lr + 8) * 2 + half] = rsum[mt][1];
            }
        }
        __syncthreads();
        if (tid < 128) ps[tid] = spr[tid * 2] + spr[tid * 2 + 1];
        return;
    }

    if (EPI == 2) {
        // rowsum gather + reciprocal
        asm volatile("cp.async.wait_group 0;" ::: "memory");
        __syncthreads();
        float* sinv = sm;
        if (tid < 128) {
            float s = 0.0f;
            for (int j = 0; j < psN; j++) s += ps[(long)j * SEQ + tid];
            sinv[tid] = 1.0f / s;
        }
        __syncthreads();
#pragma unroll
        for (int mt = 0; mt < 4; mt++) {
            int lr = wm + mt * 16 + qr;
            int r  = bm * 128 + lr;
            float i0 = sinv[lr], i1 = sinv[lr + 8];
#pragma unroll
            for (int nt = 0; nt < 8; nt++) {
                int col = bn * 128 + wn + nt * 8 + 2 * qc;
                *(float2*)&C[(long)r * ldC + col] =
                    make_float2(acc[mt][nt][0] * i0, acc[mt][nt][1] * i0);
                *(float2*)&C[(long)(r + 8) * ldC + col] =
                    make_float2(acc[mt][nt][2] * i1, acc[mt][nt][3] * i1);
            }
        }
        return;
    }

    // EPI == 0: plain store
#pragma unroll
    for (int mt = 0; mt < 4; mt++) {
        int r = bm * 128 + wm + mt * 16 + qr;
#pragma unroll
        for (int nt = 0; nt < 8; nt++) {
            int col = bn * 128 + wn + nt * 8 + 2 * qc;
            float o0 = acc[mt][nt][0] * alphaOut, o1 = acc[mt][nt][1] * alphaOut;
            float o2 = acc[mt][nt][2] * alphaOut, o3 = acc[mt][nt][3] * alphaOut;
            if (ROUND_OUT) { o0 = roundtf(o0); o1 = roundtf(o1);
                             o2 = roundtf(o2); o3 = roundtf(o3); }
            *(float2*)&C[(long)r * ldC + col]       = make_float2(o0, o1);
            *(float2*)&C[(long)(r + 8) * ldC + col] = make_float2(o2, o3);
        }
    }
}

// M = (Wq @ Wk^T) * 2^-5  (NT: both [C,H] row-major, H contiguous)
__global__ __launch_bounds__(GTHREADS, 2)
void m_gemm(const float* __restrict__ Wq, const float* __restrict__ Wk,
            float* __restrict__ M)
{
    gemm_body<0, true, true, true, false>(Wq, Wk, M, HID, HID, CIN, HID / 32,
                                          blockIdx.y, blockIdx.x, 1.0f / 32.0f,
                                          nullptr, 0, false);
}

// qm = q @ M  (NN: M is [c][c'], c' contiguous); batched over blockIdx.y
__global__ __launch_bounds__(GTHREADS, 2)
void qm_gemm(const float* __restrict__ qin, const float* __restrict__ M,
             float* __restrict__ qm)
{
    gemm_body<0, true, false, true, true>(qin, M, qm, CIN, CIN, CIN, CIN / 32,
                                          blockIdx.y, blockIdx.x, 1.0f,
                                          nullptr, 0, false);
}

// v projection (low-priority side stream). vp = v @ Wq (faithful bug).
__global__ __launch_bounds__(GTHREADS, 2)
void proj_v(const float* __restrict__ vin, const float* __restrict__ Wq,
            float* __restrict__ vp)
{
    gemm_body<0, true, false, true, true>(vin, Wq, vp, CIN, HID, HID, CIN / 32,
                                          blockIdx.y, blockIdx.x, 1.0f,
                                          nullptr, 0, false);
}

// P' = exp(qm @ k^T) with causal mask + partial row sums. k is RAW input
// (CVTB rounds fragments). Triangular grid, heavy blocks first, batched z.
__global__ __launch_bounds__(GTHREADS, 2)
void s_gemm(const float* __restrict__ qm, const float* __restrict__ kin,
            float* __restrict__ P, float* __restrict__ psum)
{
    int idx = 135 - blockIdx.x;           // heavy (high-bm) first
    int acc = 0, bm = 0;
    while (acc + bm + 1 <= idx) { acc += bm + 1; bm++; }
    int bn = idx - acc;
    const int z = blockIdx.z;
    const long ob = (long)z * SEQ * CIN;
    float* ps = psum + ((long)z * 16 + bn) * SEQ + bm * 128;
    gemm_body<1, false, true, false, false>(qm + ob, kin + ob,
                                            P + (long)z * SEQ * SEQ,
                                            CIN, CIN, SEQ, CIN / 32, bm, bn, 1.0f,
                                            ps, 0, bn == bm);
}

// out = (P' @ vp) / rowsum, K causally limited, heavy blocks first, batched z.
__global__ __launch_bounds__(GTHREADS, 2)
void pv_gemm(const float* __restrict__ P, const float* __restrict__ vp,
             float* __restrict__ out, const float* __restrict__ psum)
{
    const int bm = (int)(gridDim.y - 1 - blockIdx.y);   // heavy first
    const int bn = blockIdx.x;
    const int z  = blockIdx.z;
    const int KT = (bm + 1) * 4;
    float* ps = const_cast<float*>(psum) + (long)z * 16 * SEQ + bm * 128;
    gemm_body<2, false, false, false, true>(P + (long)z * SEQ * SEQ,
                                            vp + (long)z * SEQ * HID,
                                            out + (long)z * SEQ * HID,
                                            SEQ, HID, HID, KT, bm, bn, 1.0f,
                                            ps, bm + 1, false);
}

// ---------------- launch (R14 schedule: fork-join, batched grids) ----------
extern "C" void kernel_launch(void* const* d_in, const int* in_sizes, int n_in,
                              void* d_out, int out_size)
{
    const float* kin = (const float*)d_in[1];
    const float* qin = (const float*)d_in[2];
    const float* vin = (const float*)d_in[3];
    const float* Wk  = (const float*)d_in[4];
    const float* Wq  = (const float*)d_in[5];
    float* out = (float*)d_out;

    float *M, *qm, *vp, *P, *psum;
    cudaGetSymbolAddress((void**)&M,    g_M);
    cudaGetSymbolAddress((void**)&qm,   g_qm);
    cudaGetSymbolAddress((void**)&vp,   g_vp);
    cudaGetSymbolAddress((void**)&P,    g_P);
    cudaGetSymbolAddress((void**)&psum, g_psum);

    cudaFuncSetAttribute(m_gemm,  cudaFuncAttributeMaxDynamicSharedMemorySize, GEMM_SMEM);
    cudaFuncSetAttribute(qm_gemm, cudaFuncAttributeMaxDynamicSharedMemorySize, GEMM_SMEM);
    cudaFuncSetAttribute(proj_v,  cudaFuncAttributeMaxDynamicSharedMemorySize, GEMM_SMEM);
    cudaFuncSetAttribute(s_gemm,  cudaFuncAttributeMaxDynamicSharedMemorySize, GEMM_SMEM);
    cudaFuncSetAttribute(pv_gemm, cudaFuncAttributeMaxDynamicSharedMemorySize, GEMM_SMEM);

    const int Mrows = BATCH * SEQ;             // 8192
    dim3 gblk(GTHREADS);

    // ONE low-priority side stream + 2 events (R12-R14 passing footprint);
    // created per call, never destroyed (few calls; no device memory held).
    int loPri = 0, hiPri = 0;
    cudaDeviceGetStreamPriorityRange(&loPri, &hiPri);
    cudaStream_t s2;
    cudaStreamCreateWithPriority(&s2, cudaStreamNonBlocking, loPri);
    cudaEvent_t eFork, eJoin;
    cudaEventCreateWithFlags(&eFork, cudaEventDisableTiming);
    cudaEventCreateWithFlags(&eJoin, cudaEventDisableTiming);

    // fork
    cudaEventRecord(eFork, 0);
    cudaStreamWaitEvent(s2, eFork, 0);

    // side: v projection (backfills m_gemm/qm_gemm/s_gemm wave tails)
    proj_v<<<dim3(HID / 128, Mrows / 128, 1), gblk, GEMM_SMEM, s2>>>(vin, Wq, vp);
    cudaEventRecord(eJoin, s2);

    // critical chain: M -> qm -> P' (k-projection GEMM eliminated)
    m_gemm <<<dim3(CIN / 128, CIN / 128, 1), gblk, GEMM_SMEM>>>(Wq, Wk, M);
    qm_gemm<<<dim3(CIN / 128, Mrows / 128, 1), gblk, GEMM_SMEM>>>(qin, M, qm);
    s_gemm <<<dim3(136, 1, BATCH), gblk, GEMM_SMEM>>>(qm, kin, P, psum);

    // join: pv needs vp
    cudaStreamWaitEvent(0, eJoin, 0);
    pv_gemm<<<dim3(HID / 128, SEQ / 128, BATCH), gblk, GEMM_SMEM>>>(P, vp, out, psum);
}